// round 6
// baseline (speedup 1.0000x reference)
#include <cuda_runtime.h>
#include <cuda_bf16.h>
#include <math.h>
#include <stdint.h>

// Problem constants
constexpr int Bb = 2, Ss = 2048, Dd = 1024, Hh = 16, DH = 64;
constexpr int MM = Bb * Ss;       // 4096 rows

// ---------------- scratch (no cudaMalloc allowed) ----------------
__device__ __nv_bfloat16 g_xhi[MM * Dd];
__device__ __nv_bfloat16 g_xlo[MM * Dd];
__device__ __nv_bfloat16 g_qkvhi[MM * 3 * Dd];   // [4096, 3072]  Q|K|V
__device__ __nv_bfloat16 g_qkvlo[MM * 3 * Dd];
__device__ __nv_bfloat16 g_ahi[MM * Dd];
__device__ __nv_bfloat16 g_alo[MM * Dd];
__device__ __nv_bfloat16 g_wthi[4 * Dd * Dd];    // transposed weights [N,K], Wq|Wk|Wv|Wo
__device__ __nv_bfloat16 g_wtlo[4 * Dd * Dd];

// ================= helpers =================
__device__ __forceinline__ uint32_t smem_u32(const void* p) {
    uint32_t a;
    asm("{ .reg .u64 t; cvta.to.shared.u64 t, %1; cvt.u32.u64 %0, t; }" : "=r"(a) : "l"(p));
    return a;
}
__device__ __forceinline__ void ldsm_x4(uint32_t* r, uint32_t a) {
    asm volatile("ldmatrix.sync.aligned.m8n8.x4.shared.b16 {%0,%1,%2,%3}, [%4];"
                 : "=r"(r[0]), "=r"(r[1]), "=r"(r[2]), "=r"(r[3]) : "r"(a));
}
__device__ __forceinline__ void ldsm_x4_t(uint32_t* r, uint32_t a) {
    asm volatile("ldmatrix.sync.aligned.m8n8.x4.trans.shared.b16 {%0,%1,%2,%3}, [%4];"
                 : "=r"(r[0]), "=r"(r[1]), "=r"(r[2]), "=r"(r[3]) : "r"(a));
}
__device__ __forceinline__ void mma_bf16(float* c, const uint32_t* a, const uint32_t* b) {
    asm volatile("mma.sync.aligned.m16n8k16.row.col.f32.bf16.bf16.f32 "
                 "{%0,%1,%2,%3}, {%4,%5,%6,%7}, {%8,%9}, {%0,%1,%2,%3};"
                 : "+f"(c[0]), "+f"(c[1]), "+f"(c[2]), "+f"(c[3])
                 : "r"(a[0]), "r"(a[1]), "r"(a[2]), "r"(a[3]), "r"(b[0]), "r"(b[1]));
}
__device__ __forceinline__ void cp16(uint32_t dst, const void* src) {
    asm volatile("cp.async.cg.shared.global [%0], [%1], 16;" :: "r"(dst), "l"(src));
}
#define CP_COMMIT() asm volatile("cp.async.commit_group;" ::: "memory")
#define CP_WAIT(n)  asm volatile("cp.async.wait_group %0;" :: "n"(n) : "memory")
#define SWZ128(off) ((off) ^ (((off) >> 3) & 0x70))

__device__ __forceinline__ void split1(float x, __nv_bfloat16& h, __nv_bfloat16& l) {
    h = __float2bfloat16(x);
    l = __float2bfloat16(x - __bfloat162float(h));
}
__device__ __forceinline__ uint32_t pkbf(__nv_bfloat16 a, __nv_bfloat16 b) {
    uint16_t ua = *(uint16_t*)&a, ub = *(uint16_t*)&b;
    return (uint32_t)ua | ((uint32_t)ub << 16);
}

// ================= split kernels =================
__global__ __launch_bounds__(256) void split_f32(
    const float* __restrict__ in, __nv_bfloat16* __restrict__ hi,
    __nv_bfloat16* __restrict__ lo)
{
    int i = blockIdx.x * 256 + threadIdx.x;
    float4 v = ((const float4*)in)[i];
    __nv_bfloat16 h0, h1, h2, h3, l0, l1, l2, l3;
    split1(v.x, h0, l0); split1(v.y, h1, l1); split1(v.z, h2, l2); split1(v.w, h3, l3);
    uint2 hp, lp;
    hp.x = pkbf(h0, h1); hp.y = pkbf(h2, h3);
    lp.x = pkbf(l0, l1); lp.y = pkbf(l2, l3);
    ((uint2*)hi)[i] = hp;
    ((uint2*)lo)[i] = lp;
}

// transpose W [K,N] -> Wt [N,K] bf16 hi/lo, for 4 weights (blockIdx.z)
__global__ __launch_bounds__(256) void transpose_split(
    const float* __restrict__ W0, const float* __restrict__ W1,
    const float* __restrict__ W2, const float* __restrict__ W3,
    __nv_bfloat16* __restrict__ hi, __nv_bfloat16* __restrict__ lo)
{
    __shared__ float sm[32][33];
    const float* W = (blockIdx.z == 0) ? W0 : (blockIdx.z == 1) ? W1 : (blockIdx.z == 2) ? W2 : W3;
    const int tx = threadIdx.x, ty = threadIdx.y;
    const int k0 = blockIdx.y * 32, n0 = blockIdx.x * 32;
#pragma unroll
    for (int i = 0; i < 4; i++)
        sm[ty + 8 * i][tx] = W[(size_t)(k0 + ty + 8 * i) * Dd + n0 + tx];
    __syncthreads();
    size_t zb = (size_t)blockIdx.z * Dd * Dd;
#pragma unroll
    for (int i = 0; i < 4; i++) {
        float v = sm[tx][ty + 8 * i];
        __nv_bfloat16 h, l; split1(v, h, l);
        size_t o = zb + (size_t)(n0 + ty + 8 * i) * Dd + k0 + tx;
        hi[o] = h; lo[o] = l;
    }
}

// ================= mma.sync GEMM (512 threads) =================
// C[M, NS] = A[M,1024] @ Bt[NS,1024]^T + bias (bias selected per 1024-col group).
// 3-term bf16 emulation of fp32. CTA tile 128x128, BK=64, double-buffered cp.async.
// 16 warps: grid 4(m) x 4(n), warp tile 32x32 -> 2 m16 x 4 n8 mma tiles.
constexpr int BM = 128, BN = 128, BKC = 64;
constexpr int STG_BYTES = 65536;
constexpr int OFF_AHI = 0, OFF_ALO = 16384, OFF_BHI = 32768, OFF_BLO = 49152;
constexpr int GEMM_SMEM = 2 * STG_BYTES + 1024;

template<bool HL>
__global__ __launch_bounds__(512, 1) void gemm_mma(
    const __nv_bfloat16* __restrict__ Ahi, const __nv_bfloat16* __restrict__ Alo,
    const __nv_bfloat16* __restrict__ Bhi, const __nv_bfloat16* __restrict__ Blo,
    const float* __restrict__ bias0, const float* __restrict__ bias1,
    const float* __restrict__ bias2,
    int NS, float* __restrict__ C,
    __nv_bfloat16* __restrict__ Chi, __nv_bfloat16* __restrict__ Clo)
{
    extern __shared__ char smc[];
    uint32_t sraw = smem_u32(smc);
    uint32_t sb = (sraw + 1023u) & ~1023u;

    const int tid = threadIdx.x, lid = tid & 31, wid = tid >> 5;
    const int wm = wid >> 2, wn = wid & 3;
    const int m0 = blockIdx.y * BM, n0 = blockIdx.x * BN;
    const int z = n0 >> 10;
    const float* bias = (z == 0) ? bias0 : ((z == 1) ? bias1 : bias2);

    // cp.async: 2 chunks per thread per array
    uint32_t dsto[2];
    int rowA[2], rowB[2];
    uint32_t coff[2];
#pragma unroll
    for (int i = 0; i < 2; i++) {
        int idx = tid + i * 512;
        int r = idx >> 3;
        uint32_t off = (uint32_t)(r * 128 + (idx & 7) * 16);
        dsto[i] = SWZ128(off);
        rowA[i] = m0 + r;
        rowB[i] = n0 + r;
        coff[i] = (uint32_t)((idx & 7) * 16);
    }

    auto prefetch = [&](int chunk, int s) {
        uint32_t st = sb + s * STG_BYTES;
        size_t kb = (size_t)chunk * BKC * 2;
#pragma unroll
        for (int i = 0; i < 2; i++) {
            size_t ga = (size_t)rowA[i] * (Dd * 2) + kb + coff[i];
            size_t gb = (size_t)rowB[i] * (Dd * 2) + kb + coff[i];
            cp16(st + OFF_AHI + dsto[i], (const char*)Ahi + ga);
            cp16(st + OFF_ALO + dsto[i], (const char*)Alo + ga);
            cp16(st + OFF_BHI + dsto[i], (const char*)Bhi + gb);
            cp16(st + OFF_BLO + dsto[i], (const char*)Blo + gb);
        }
    };

    float acc[2][4][4];
#pragma unroll
    for (int mt = 0; mt < 2; mt++)
#pragma unroll
        for (int nt = 0; nt < 4; nt++)
#pragma unroll
            for (int e = 0; e < 4; e++) acc[mt][nt][e] = 0.f;

    prefetch(0, 0);
    CP_COMMIT();

    const int a_row = wm * 32 + (lid & 15);
    const uint32_t a_cb = (uint32_t)(((lid >> 4) & 1) * 16);
    const int mg = lid >> 3;
    const int b_row0 = wn * 32 + (mg >> 1) * 8 + (lid & 7);
    const uint32_t b_cb = (uint32_t)((mg & 1) * 16);

    const int NIT = Dd / BKC;   // 16
    for (int it = 0; it < NIT; it++) {
        const int s = it & 1;
        if (it + 1 < NIT) {
            prefetch(it + 1, (it + 1) & 1);
            CP_COMMIT();
            CP_WAIT(1);
        } else {
            CP_WAIT(0);
        }
        __syncthreads();

        uint32_t st = sb + s * STG_BYTES;
#pragma unroll
        for (int kt = 0; kt < 4; kt++) {
            uint32_t ah[2][4], al[2][4];
#pragma unroll
            for (int mt = 0; mt < 2; mt++) {
                uint32_t off = (uint32_t)((a_row + mt * 16) * 128) + kt * 32 + a_cb;
                off = SWZ128(off);
                ldsm_x4(ah[mt], st + OFF_AHI + off);
                ldsm_x4(al[mt], st + OFF_ALO + off);
            }
            uint32_t bh[4][2], bl[4][2];
#pragma unroll
            for (int p = 0; p < 2; p++) {
                uint32_t off = (uint32_t)((b_row0 + p * 16) * 128) + kt * 32 + b_cb;
                off = SWZ128(off);
                uint32_t r[4];
                ldsm_x4(r, st + OFF_BHI + off);
                bh[2 * p][0] = r[0]; bh[2 * p][1] = r[1];
                bh[2 * p + 1][0] = r[2]; bh[2 * p + 1][1] = r[3];
                ldsm_x4(r, st + OFF_BLO + off);
                bl[2 * p][0] = r[0]; bl[2 * p][1] = r[1];
                bl[2 * p + 1][0] = r[2]; bl[2 * p + 1][1] = r[3];
            }
#pragma unroll
            for (int mt = 0; mt < 2; mt++)
#pragma unroll
                for (int nt = 0; nt < 4; nt++) {
                    mma_bf16(acc[mt][nt], ah[mt], bh[nt]);
                    mma_bf16(acc[mt][nt], ah[mt], bl[nt]);
                    mma_bf16(acc[mt][nt], al[mt], bh[nt]);
                }
        }
        __syncthreads();
    }

    // epilogue
#pragma unroll
    for (int nt = 0; nt < 4; nt++) {
        int c0 = n0 + wn * 32 + nt * 8 + (lid & 3) * 2;
        float b0 = bias[c0 & 1023], b1 = bias[(c0 + 1) & 1023];
#pragma unroll
        for (int mt = 0; mt < 2; mt++) {
            int r0 = m0 + wm * 32 + mt * 16 + (lid >> 2);
            float v0 = acc[mt][nt][0] + b0, v1 = acc[mt][nt][1] + b1;
            float v2 = acc[mt][nt][2] + b0, v3 = acc[mt][nt][3] + b1;
            if (HL) {
                __nv_bfloat16 h0, h1, h2, h3, l0, l1, l2, l3;
                split1(v0, h0, l0); split1(v1, h1, l1);
                split1(v2, h2, l2); split1(v3, h3, l3);
                *(uint32_t*)&Chi[(size_t)r0 * NS + c0] = pkbf(h0, h1);
                *(uint32_t*)&Clo[(size_t)r0 * NS + c0] = pkbf(l0, l1);
                *(uint32_t*)&Chi[(size_t)(r0 + 8) * NS + c0] = pkbf(h2, h3);
                *(uint32_t*)&Clo[(size_t)(r0 + 8) * NS + c0] = pkbf(l2, l3);
            } else {
                float2 w0 = {v0, v1}, w1 = {v2, v3};
                *(float2*)&C[(size_t)r0 * NS + c0] = w0;
                *(float2*)&C[(size_t)(r0 + 8) * NS + c0] = w1;
            }
        }
    }
}

// ================= Flash attention with mma.sync (causal) =================
// Reads Q/K/V from the combined [4096, 3072] hi/lo buffer (row stride 3072).
constexpr int AT_STG = 32768;                      // Khi|Klo|Vhi|Vlo 8KB each
constexpr int A_QZ = 2 * AT_STG;                   // Q hi 16K + lo 16K (reused for out staging)
constexpr int ATT_SMEM = A_QZ + 32768 + 1024;
constexpr float SCL = 0.03125f;                    // 1/sqrt(1024)
constexpr int QKV_RS = 3 * Dd * 2;                 // row stride bytes = 6144

__global__ __launch_bounds__(256, 1) void attn_mma(
    const __nv_bfloat16* __restrict__ qkvhi, const __nv_bfloat16* __restrict__ qkvlo,
    __nv_bfloat16* __restrict__ ohi, __nv_bfloat16* __restrict__ olo)
{
    extern __shared__ char smc[];
    uint32_t sraw = smem_u32(smc);
    uint32_t sb = (sraw + 1023u) & ~1023u;
    char* smb = smc + (sb - sraw);

    const int tid = threadIdx.x, lid = tid & 31, wq = tid >> 5;
    const int qi = blockIdx.x, bh = blockIdx.y;
    const int b = bh >> 4, h = bh & 15;
    const int q0 = qi * 128;
    const size_t qoff2 = ((size_t)b * Ss * (3 * Dd) + (size_t)h * DH) * 2;   // bytes
    const char* hb = (const char*)qkvhi + qoff2;
    const char* lb = (const char*)qkvlo + qoff2;
    const size_t obase2 = ((size_t)b * Ss * Dd + (size_t)h * DH) * 2;        // output bytes

    // Q load: 128 rows x 8 chunks x 2 arrays
#pragma unroll
    for (int i = 0; i < 8; i++) {
        int idx = tid + i * 256;
        int arr = idx >> 10, c = idx & 1023;
        int row = c >> 3; uint32_t colb = (uint32_t)((c & 7) * 16);
        const char* src = (arr ? lb : hb) + (size_t)(q0 + row) * QKV_RS + colb;
        cp16(sb + A_QZ + arr * 16384 + SWZ128((uint32_t)(row * 128) + colb), src);
    }
    CP_COMMIT();

    const char* kvsrc[4] = {hb + 2048, lb + 2048, hb + 4096, lb + 4096};  // Khi,Klo,Vhi,Vlo
    auto kvload = [&](int kt, int s) {
        uint32_t st = sb + s * AT_STG;
        int kv0 = kt * 64;
#pragma unroll
        for (int i = 0; i < 8; i++) {
            int idx = tid + i * 256;
            int arr = idx >> 9, c = idx & 511;
            int row = c >> 3; uint32_t colb = (uint32_t)((c & 7) * 16);
            cp16(st + arr * 8192 + SWZ128((uint32_t)(row * 128) + colb),
                 kvsrc[arr] + (size_t)(kv0 + row) * QKV_RS + colb);
        }
    };
    kvload(0, 0);
    CP_COMMIT();
    CP_WAIT(1);          // Q done
    __syncthreads();

    // Q fragments -> registers (4 dim-chunks of 16)
    uint32_t qh[4][4], ql[4][4];
    {
        const int a_row = wq * 16 + (lid & 15);
        const uint32_t a_cb = (uint32_t)(((lid >> 4) & 1) * 16);
#pragma unroll
        for (int kd = 0; kd < 4; kd++) {
            uint32_t off = SWZ128((uint32_t)(a_row * 128) + kd * 32 + a_cb);
            ldsm_x4(qh[kd], sb + A_QZ + off);
            ldsm_x4(ql[kd], sb + A_QZ + 16384 + off);
        }
    }

    float o[8][4];
#pragma unroll
    for (int nt = 0; nt < 8; nt++)
#pragma unroll
        for (int e = 0; e < 4; e++) o[nt][e] = 0.f;
    float m0v = -INFINITY, m1v = -INFINITY, lsum0 = 0.f, lsum1 = 0.f;

    const int r0g = q0 + wq * 16 + (lid >> 2);
    const int r1g = r0g + 8;
    const int mg = lid >> 3;
    const int krow = (mg >> 1) * 8 + (lid & 7);
    const uint32_t kcb = (uint32_t)((mg & 1) * 16);
    const int vrow = lid & 15;
    const uint32_t vcb = (uint32_t)((lid >> 4) * 16);

    const int nkt = 2 * qi + 2;
    for (int kt = 0; kt < nkt; kt++) {
        if (kt + 1 < nkt) { kvload(kt + 1, (kt + 1) & 1); CP_COMMIT(); CP_WAIT(1); }
        else CP_WAIT(0);
        __syncthreads();
        uint32_t st = sb + (kt & 1) * AT_STG;

        // S = Q K^T (3-term)
        float s[8][4];
#pragma unroll
        for (int nt = 0; nt < 8; nt++)
#pragma unroll
            for (int e = 0; e < 4; e++) s[nt][e] = 0.f;
#pragma unroll
        for (int kd = 0; kd < 4; kd++) {
#pragma unroll
            for (int np = 0; np < 4; np++) {
                uint32_t off = SWZ128((uint32_t)((np * 16 + krow) * 128) + kd * 32 + kcb);
                uint32_t bh_[4], bl_[4];
                ldsm_x4(bh_, st + 0 + off);
                ldsm_x4(bl_, st + 8192 + off);
                mma_bf16(s[2 * np],     qh[kd], bh_);
                mma_bf16(s[2 * np],     qh[kd], bl_);
                mma_bf16(s[2 * np],     ql[kd], bh_);
                mma_bf16(s[2 * np + 1], qh[kd], bh_ + 2);
                mma_bf16(s[2 * np + 1], qh[kd], bl_ + 2);
                mma_bf16(s[2 * np + 1], ql[kd], bh_ + 2);
            }
        }

        // scale + causal mask + row max
        const int kv0 = kt * 64;
        float tm0 = -INFINITY, tm1 = -INFINITY;
#pragma unroll
        for (int nt = 0; nt < 8; nt++) {
            int kg = kv0 + nt * 8 + (lid & 3) * 2;
            s[nt][0] = (kg     <= r0g) ? s[nt][0] * SCL : -INFINITY;
            s[nt][1] = (kg + 1 <= r0g) ? s[nt][1] * SCL : -INFINITY;
            s[nt][2] = (kg     <= r1g) ? s[nt][2] * SCL : -INFINITY;
            s[nt][3] = (kg + 1 <= r1g) ? s[nt][3] * SCL : -INFINITY;
            tm0 = fmaxf(tm0, fmaxf(s[nt][0], s[nt][1]));
            tm1 = fmaxf(tm1, fmaxf(s[nt][2], s[nt][3]));
        }
        tm0 = fmaxf(tm0, __shfl_xor_sync(0xffffffffu, tm0, 1));
        tm0 = fmaxf(tm0, __shfl_xor_sync(0xffffffffu, tm0, 2));
        tm1 = fmaxf(tm1, __shfl_xor_sync(0xffffffffu, tm1, 1));
        tm1 = fmaxf(tm1, __shfl_xor_sync(0xffffffffu, tm1, 2));

        float mn0 = fmaxf(m0v, tm0), mn1 = fmaxf(m1v, tm1);
        float sc0 = __expf(m0v - mn0), sc1 = __expf(m1v - mn1);
        m0v = mn0; m1v = mn1;

        // P = exp(S - m), build bf16 hi/lo A-fragments
        uint32_t pah[4][4], pal[4][4];
        float ts0 = 0.f, ts1 = 0.f;
#pragma unroll
        for (int nt = 0; nt < 8; nt++) {
            float p0 = __expf(s[nt][0] - mn0);
            float p1 = __expf(s[nt][1] - mn0);
            float p2 = __expf(s[nt][2] - mn1);
            float p3 = __expf(s[nt][3] - mn1);
            ts0 += p0 + p1; ts1 += p2 + p3;
            __nv_bfloat16 h0, h1, h2, h3, l0, l1, l2, l3;
            split1(p0, h0, l0); split1(p1, h1, l1);
            split1(p2, h2, l2); split1(p3, h3, l3);
            int kp = nt >> 1, e = (nt & 1) * 2;
            pah[kp][e] = pkbf(h0, h1); pah[kp][e + 1] = pkbf(h2, h3);
            pal[kp][e] = pkbf(l0, l1); pal[kp][e + 1] = pkbf(l2, l3);
        }
        ts0 += __shfl_xor_sync(0xffffffffu, ts0, 1);
        ts0 += __shfl_xor_sync(0xffffffffu, ts0, 2);
        ts1 += __shfl_xor_sync(0xffffffffu, ts1, 1);
        ts1 += __shfl_xor_sync(0xffffffffu, ts1, 2);
        lsum0 = lsum0 * sc0 + ts0;
        lsum1 = lsum1 * sc1 + ts1;
#pragma unroll
        for (int nt = 0; nt < 8; nt++) {
            o[nt][0] *= sc0; o[nt][1] *= sc0;
            o[nt][2] *= sc1; o[nt][3] *= sc1;
        }

        // O += P V (3-term); V fragments via ldmatrix.trans
#pragma unroll
        for (int kp = 0; kp < 4; kp++) {
#pragma unroll
            for (int np = 0; np < 4; np++) {
                uint32_t off = SWZ128((uint32_t)((kp * 16 + vrow) * 128) + np * 32 + vcb);
                uint32_t vh_[4], vl_[4];
                ldsm_x4_t(vh_, st + 16384 + off);
                ldsm_x4_t(vl_, st + 24576 + off);
                mma_bf16(o[2 * np],     pah[kp], vh_);
                mma_bf16(o[2 * np],     pah[kp], vl_);
                mma_bf16(o[2 * np],     pal[kp], vh_);
                mma_bf16(o[2 * np + 1], pah[kp], vh_ + 2);
                mma_bf16(o[2 * np + 1], pah[kp], vl_ + 2);
                mma_bf16(o[2 * np + 1], pal[kp], vh_ + 2);
            }
        }
        __syncthreads();
    }

    // epilogue: normalize, hi/lo split, stage in smem, coalesced store
    float il0 = 1.f / lsum0, il1 = 1.f / lsum1;
    {
        int rs0 = wq * 16 + (lid >> 2);
#pragma unroll
        for (int nt = 0; nt < 8; nt++) {
            uint32_t colb = (uint32_t)(nt * 16 + (lid & 3) * 4);
            float v0 = o[nt][0] * il0, v1 = o[nt][1] * il0;
            float v2 = o[nt][2] * il1, v3 = o[nt][3] * il1;
            __nv_bfloat16 h0, h1, h2, h3, l0, l1, l2, l3;
            split1(v0, h0, l0); split1(v1, h1, l1);
            split1(v2, h2, l2); split1(v3, h3, l3);
            *(uint32_t*)(smb + A_QZ + rs0 * 128 + colb) = pkbf(h0, h1);
            *(uint32_t*)(smb + A_QZ + (rs0 + 8) * 128 + colb) = pkbf(h2, h3);
            *(uint32_t*)(smb + A_QZ + 16384 + rs0 * 128 + colb) = pkbf(l0, l1);
            *(uint32_t*)(smb + A_QZ + 16384 + (rs0 + 8) * 128 + colb) = pkbf(l2, l3);
        }
    }
    __syncthreads();
#pragma unroll
    for (int i = 0; i < 8; i++) {
        int idx = tid + i * 256;
        int arr = idx >> 10, c = idx & 1023;
        int row = c >> 3; uint32_t colb = (uint32_t)((c & 7) * 16);
        uint4 v = *(uint4*)(smb + A_QZ + arr * 16384 + row * 128 + colb);
        char* dst = (char*)(arr ? olo : ohi) + obase2 + (size_t)(q0 + row) * 2048 + colb;
        *(uint4*)dst = v;
    }
}

// ---------------- launch ----------------
extern "C" void kernel_launch(void* const* d_in, const int* in_sizes, int n_in,
                              void* d_out, int out_size)
{
    const float* x  = (const float*)d_in[0];
    const float* Wq = (const float*)d_in[1];
    const float* bq = (const float*)d_in[2];
    const float* Wk = (const float*)d_in[3];
    const float* bk = (const float*)d_in[4];
    const float* Wv = (const float*)d_in[5];
    const float* bv = (const float*)d_in[6];
    const float* Wo = (const float*)d_in[7];
    const float* bo = (const float*)d_in[8];
    float* out = (float*)d_out;

    __nv_bfloat16 *xhi, *xlo, *qkvhi, *qkvlo, *ahi, *alo, *wthi, *wtlo;
    cudaGetSymbolAddress((void**)&xhi,   g_xhi);
    cudaGetSymbolAddress((void**)&xlo,   g_xlo);
    cudaGetSymbolAddress((void**)&qkvhi, g_qkvhi);
    cudaGetSymbolAddress((void**)&qkvlo, g_qkvlo);
    cudaGetSymbolAddress((void**)&ahi,   g_ahi);
    cudaGetSymbolAddress((void**)&alo,   g_alo);
    cudaGetSymbolAddress((void**)&wthi,  g_wthi);
    cudaGetSymbolAddress((void**)&wtlo,  g_wtlo);

    cudaFuncSetAttribute(gemm_mma<true>,
                         cudaFuncAttributeMaxDynamicSharedMemorySize, GEMM_SMEM);
    cudaFuncSetAttribute(gemm_mma<false>,
                         cudaFuncAttributeMaxDynamicSharedMemorySize, GEMM_SMEM);
    cudaFuncSetAttribute(attn_mma,
                         cudaFuncAttributeMaxDynamicSharedMemorySize, ATT_SMEM);

    const int WSZ = Dd * Dd;

    transpose_split<<<dim3(32, 32, 4), dim3(32, 8)>>>(Wq, Wk, Wv, Wo, wthi, wtlo);
    split_f32<<<(MM * Dd) / 1024, 256>>>(x, xhi, xlo);

    // Fused QKV projection: C[4096, 3072] over concatenated [Wq;Wk;Wv]
    gemm_mma<true><<<dim3(3 * Dd / BN, MM / BM), 512, GEMM_SMEM>>>(
        xhi, xlo, wthi, wtlo, bq, bk, bv, 3 * Dd, nullptr, qkvhi, qkvlo);

    attn_mma<<<dim3(Ss / 128, Bb * Hh), 256, ATT_SMEM>>>(qkvhi, qkvlo, ahi, alo);

    // Output projection
    gemm_mma<false><<<dim3(Dd / BN, MM / BM), 512, GEMM_SMEM>>>(
        ahi, alo, wthi + 3 * WSZ, wtlo + 3 * WSZ, bo, bo, bo, Dd, out, nullptr, nullptr);
}

// round 7
// speedup vs baseline: 1.0502x; 1.0502x over previous
#include <cuda_runtime.h>
#include <cuda_bf16.h>
#include <math.h>
#include <stdint.h>

// Problem constants
constexpr int Bb = 2, Ss = 2048, Dd = 1024, Hh = 16, DH = 64;
constexpr int MM = Bb * Ss;       // 4096 rows

// ---------------- scratch (no cudaMalloc allowed) ----------------
__device__ __nv_bfloat16 g_xhi[MM * Dd];
__device__ __nv_bfloat16 g_xlo[MM * Dd];
__device__ __nv_bfloat16 g_qhi[MM * Dd];
__device__ __nv_bfloat16 g_qlo[MM * Dd];
__device__ __nv_bfloat16 g_khi[MM * Dd];
__device__ __nv_bfloat16 g_klo[MM * Dd];
__device__ __nv_bfloat16 g_vhi[MM * Dd];
__device__ __nv_bfloat16 g_vlo[MM * Dd];
__device__ __nv_bfloat16 g_ahi[MM * Dd];
__device__ __nv_bfloat16 g_alo[MM * Dd];
__device__ __nv_bfloat16 g_wthi[4 * Dd * Dd];    // transposed weights [N,K], Wq|Wk|Wv|Wo
__device__ __nv_bfloat16 g_wtlo[4 * Dd * Dd];

// ================= helpers =================
__device__ __forceinline__ uint32_t smem_u32(const void* p) {
    uint32_t a;
    asm("{ .reg .u64 t; cvta.to.shared.u64 t, %1; cvt.u32.u64 %0, t; }" : "=r"(a) : "l"(p));
    return a;
}
__device__ __forceinline__ void ldsm_x4(uint32_t* r, uint32_t a) {
    asm volatile("ldmatrix.sync.aligned.m8n8.x4.shared.b16 {%0,%1,%2,%3}, [%4];"
                 : "=r"(r[0]), "=r"(r[1]), "=r"(r[2]), "=r"(r[3]) : "r"(a));
}
__device__ __forceinline__ void ldsm_x4_t(uint32_t* r, uint32_t a) {
    asm volatile("ldmatrix.sync.aligned.m8n8.x4.trans.shared.b16 {%0,%1,%2,%3}, [%4];"
                 : "=r"(r[0]), "=r"(r[1]), "=r"(r[2]), "=r"(r[3]) : "r"(a));
}
__device__ __forceinline__ void mma_bf16(float* c, const uint32_t* a, const uint32_t* b) {
    asm volatile("mma.sync.aligned.m16n8k16.row.col.f32.bf16.bf16.f32 "
                 "{%0,%1,%2,%3}, {%4,%5,%6,%7}, {%8,%9}, {%0,%1,%2,%3};"
                 : "+f"(c[0]), "+f"(c[1]), "+f"(c[2]), "+f"(c[3])
                 : "r"(a[0]), "r"(a[1]), "r"(a[2]), "r"(a[3]), "r"(b[0]), "r"(b[1]));
}
__device__ __forceinline__ void cp16(uint32_t dst, const void* src) {
    asm volatile("cp.async.cg.shared.global [%0], [%1], 16;" :: "r"(dst), "l"(src));
}
#define CP_COMMIT() asm volatile("cp.async.commit_group;" ::: "memory")
#define CP_WAIT(n)  asm volatile("cp.async.wait_group %0;" :: "n"(n) : "memory")
#define SWZ128(off) ((off) ^ (((off) >> 3) & 0x70))

__device__ __forceinline__ void split1(float x, __nv_bfloat16& h, __nv_bfloat16& l) {
    h = __float2bfloat16(x);
    l = __float2bfloat16(x - __bfloat162float(h));
}
__device__ __forceinline__ uint32_t pkbf(__nv_bfloat16 a, __nv_bfloat16 b) {
    uint16_t ua = *(uint16_t*)&a, ub = *(uint16_t*)&b;
    return (uint32_t)ua | ((uint32_t)ub << 16);
}

// ================= split kernels =================
__global__ __launch_bounds__(256) void split_f32(
    const float* __restrict__ in, __nv_bfloat16* __restrict__ hi,
    __nv_bfloat16* __restrict__ lo)
{
    int i = blockIdx.x * 256 + threadIdx.x;
    float4 v = ((const float4*)in)[i];
    __nv_bfloat16 h0, h1, h2, h3, l0, l1, l2, l3;
    split1(v.x, h0, l0); split1(v.y, h1, l1); split1(v.z, h2, l2); split1(v.w, h3, l3);
    uint2 hp, lp;
    hp.x = pkbf(h0, h1); hp.y = pkbf(h2, h3);
    lp.x = pkbf(l0, l1); lp.y = pkbf(l2, l3);
    ((uint2*)hi)[i] = hp;
    ((uint2*)lo)[i] = lp;
}

// transpose W [K,N] -> Wt [N,K] bf16 hi/lo, for 4 weights (blockIdx.z)
__global__ __launch_bounds__(256) void transpose_split(
    const float* __restrict__ W0, const float* __restrict__ W1,
    const float* __restrict__ W2, const float* __restrict__ W3,
    __nv_bfloat16* __restrict__ hi, __nv_bfloat16* __restrict__ lo)
{
    __shared__ float sm[32][33];
    const float* W = (blockIdx.z == 0) ? W0 : (blockIdx.z == 1) ? W1 : (blockIdx.z == 2) ? W2 : W3;
    const int tx = threadIdx.x, ty = threadIdx.y;
    const int k0 = blockIdx.y * 32, n0 = blockIdx.x * 32;
#pragma unroll
    for (int i = 0; i < 4; i++)
        sm[ty + 8 * i][tx] = W[(size_t)(k0 + ty + 8 * i) * Dd + n0 + tx];
    __syncthreads();
    size_t zb = (size_t)blockIdx.z * Dd * Dd;
#pragma unroll
    for (int i = 0; i < 4; i++) {
        float v = sm[tx][ty + 8 * i];
        __nv_bfloat16 h, l; split1(v, h, l);
        size_t o = zb + (size_t)(n0 + ty + 8 * i) * Dd + k0 + tx;
        hi[o] = h; lo[o] = l;
    }
}

// ================= mma.sync GEMM (256 threads, known-good config) =================
// MODE 0: QKV. grid (24, 32); z = blockIdx.x>>3 selects Wq/Wk/Wv and q/k/v hi-lo outputs.
// MODE 1: O projection. grid (8, 32); fp32 output to C.
// 3-term bf16 emulation of fp32. CTA tile 128x128, BK=64, double-buffered cp.async.
// 8 warps: grid 2(m) x 4(n), warp tile 64x32 -> 4 m16 x 4 n8 mma tiles.
constexpr int BM = 128, BN = 128, BKC = 64;
constexpr int STG_BYTES = 65536;
constexpr int OFF_AHI = 0, OFF_ALO = 16384, OFF_BHI = 32768, OFF_BLO = 49152;
constexpr int GEMM_SMEM = 2 * STG_BYTES + 1024;

template<int MODE>
__global__ __launch_bounds__(256, 1) void gemm_mma(
    const float* __restrict__ bias0, const float* __restrict__ bias1,
    const float* __restrict__ bias2, float* __restrict__ C)
{
    extern __shared__ char smc[];
    uint32_t sraw = smem_u32(smc);
    uint32_t sb = (sraw + 1023u) & ~1023u;

    const int tid = threadIdx.x, lid = tid & 31, wid = tid >> 5;
    const int wm = wid >> 2, wn = wid & 3;
    const int m0 = blockIdx.y * BM;
    const int z = (MODE == 0) ? (blockIdx.x >> 3) : 3;
    const int n0 = (MODE == 0) ? ((blockIdx.x & 7) * BN) : (blockIdx.x * BN);

    const __nv_bfloat16* Ahi = (MODE == 0) ? g_xhi : g_ahi;
    const __nv_bfloat16* Alo = (MODE == 0) ? g_xlo : g_alo;
    const __nv_bfloat16* Bhi = g_wthi + (size_t)z * Dd * Dd;
    const __nv_bfloat16* Blo = g_wtlo + (size_t)z * Dd * Dd;
    const float* bias = (MODE == 1) ? bias0 : ((z == 0) ? bias0 : (z == 1) ? bias1 : bias2);
    __nv_bfloat16* Chi = nullptr;
    __nv_bfloat16* Clo = nullptr;
    if (MODE == 0) {
        Chi = (z == 0) ? g_qhi : (z == 1) ? g_khi : g_vhi;
        Clo = (z == 0) ? g_qlo : (z == 1) ? g_klo : g_vlo;
    }

    uint32_t dsto[4];
    int rowA[4], rowB[4];
    uint32_t coff[4];
#pragma unroll
    for (int i = 0; i < 4; i++) {
        int idx = tid + i * 256;
        int r = idx >> 3;
        uint32_t off = (uint32_t)(r * 128 + (idx & 7) * 16);
        dsto[i] = SWZ128(off);
        rowA[i] = m0 + r;
        rowB[i] = n0 + r;
        coff[i] = (uint32_t)((idx & 7) * 16);
    }

    auto prefetch = [&](int chunk, int s) {
        uint32_t st = sb + s * STG_BYTES;
        size_t kb = (size_t)chunk * BKC * 2;
#pragma unroll
        for (int i = 0; i < 4; i++) {
            size_t ga = (size_t)rowA[i] * (Dd * 2) + kb + coff[i];
            size_t gb = (size_t)rowB[i] * (Dd * 2) + kb + coff[i];
            cp16(st + OFF_AHI + dsto[i], (const char*)Ahi + ga);
            cp16(st + OFF_ALO + dsto[i], (const char*)Alo + ga);
            cp16(st + OFF_BHI + dsto[i], (const char*)Bhi + gb);
            cp16(st + OFF_BLO + dsto[i], (const char*)Blo + gb);
        }
    };

    float acc[4][4][4];
#pragma unroll
    for (int mt = 0; mt < 4; mt++)
#pragma unroll
        for (int nt = 0; nt < 4; nt++)
#pragma unroll
            for (int e = 0; e < 4; e++) acc[mt][nt][e] = 0.f;

    prefetch(0, 0);
    CP_COMMIT();

    const int a_row = wm * 64 + (lid & 15);
    const uint32_t a_cb = (uint32_t)(((lid >> 4) & 1) * 16);
    const int mg = lid >> 3;
    const int b_row0 = wn * 32 + (mg >> 1) * 8 + (lid & 7);
    const uint32_t b_cb = (uint32_t)((mg & 1) * 16);

    const int NIT = Dd / BKC;   // 16
    for (int it = 0; it < NIT; it++) {
        const int s = it & 1;
        if (it + 1 < NIT) {
            prefetch(it + 1, (it + 1) & 1);
            CP_COMMIT();
            CP_WAIT(1);
        } else {
            CP_WAIT(0);
        }
        __syncthreads();

        uint32_t st = sb + s * STG_BYTES;
#pragma unroll
        for (int kt = 0; kt < 4; kt++) {
            uint32_t ah[4][4], al[4][4];
#pragma unroll
            for (int mt = 0; mt < 4; mt++) {
                uint32_t off = (uint32_t)((a_row + mt * 16) * 128) + kt * 32 + a_cb;
                off = SWZ128(off);
                ldsm_x4(ah[mt], st + OFF_AHI + off);
                ldsm_x4(al[mt], st + OFF_ALO + off);
            }
            uint32_t bh[4][2], bl[4][2];
#pragma unroll
            for (int p = 0; p < 2; p++) {
                uint32_t off = (uint32_t)((b_row0 + p * 16) * 128) + kt * 32 + b_cb;
                off = SWZ128(off);
                uint32_t r[4];
                ldsm_x4(r, st + OFF_BHI + off);
                bh[2 * p][0] = r[0]; bh[2 * p][1] = r[1];
                bh[2 * p + 1][0] = r[2]; bh[2 * p + 1][1] = r[3];
                ldsm_x4(r, st + OFF_BLO + off);
                bl[2 * p][0] = r[0]; bl[2 * p][1] = r[1];
                bl[2 * p + 1][0] = r[2]; bl[2 * p + 1][1] = r[3];
            }
#pragma unroll
            for (int mt = 0; mt < 4; mt++)
#pragma unroll
                for (int nt = 0; nt < 4; nt++) {
                    mma_bf16(acc[mt][nt], ah[mt], bh[nt]);
                    mma_bf16(acc[mt][nt], ah[mt], bl[nt]);
                    mma_bf16(acc[mt][nt], al[mt], bh[nt]);
                }
        }
        __syncthreads();
    }

    // epilogue
#pragma unroll
    for (int nt = 0; nt < 4; nt++) {
        int c0 = n0 + wn * 32 + nt * 8 + (lid & 3) * 2;
        float b0 = bias[c0], b1 = bias[c0 + 1];
#pragma unroll
        for (int mt = 0; mt < 4; mt++) {
            int r0 = m0 + wm * 64 + mt * 16 + (lid >> 2);
            float v0 = acc[mt][nt][0] + b0, v1 = acc[mt][nt][1] + b1;
            float v2 = acc[mt][nt][2] + b0, v3 = acc[mt][nt][3] + b1;
            if (MODE == 0) {
                __nv_bfloat16 h0, h1, h2, h3, l0, l1, l2, l3;
                split1(v0, h0, l0); split1(v1, h1, l1);
                split1(v2, h2, l2); split1(v3, h3, l3);
                *(uint32_t*)&Chi[(size_t)r0 * Dd + c0] = pkbf(h0, h1);
                *(uint32_t*)&Clo[(size_t)r0 * Dd + c0] = pkbf(l0, l1);
                *(uint32_t*)&Chi[(size_t)(r0 + 8) * Dd + c0] = pkbf(h2, h3);
                *(uint32_t*)&Clo[(size_t)(r0 + 8) * Dd + c0] = pkbf(l2, l3);
            } else {
                float2 w0 = {v0, v1}, w1 = {v2, v3};
                *(float2*)&C[(size_t)r0 * Dd + c0] = w0;
                *(float2*)&C[(size_t)(r0 + 8) * Dd + c0] = w1;
            }
        }
    }
}

// ================= Flash attention with mma.sync (causal) =================
// 3-stage KV pipeline; contiguous q/k/v hi/lo inputs; mask-free fast path for
// fully-unmasked tiles.
constexpr int AT_STG = 32768;                      // Khi|Klo|Vhi|Vlo 8KB each
constexpr int A_QZ = 3 * AT_STG;                   // Q hi 16K + lo 16K (reused for out staging)
constexpr int ATT_SMEM = A_QZ + 32768 + 1024;
constexpr float SCL = 0.03125f;                    // 1/sqrt(1024)

template<bool MASK>
__device__ __forceinline__ void attn_tile(
    uint32_t st, int kv0, int r0g, int r1g, int lid,
    int krow, uint32_t kcb, int vrow, uint32_t vcb,
    const uint32_t (&qh)[4][4], const uint32_t (&ql)[4][4],
    uint32_t qz,
    float (&o)[8][4], float& m0v, float& m1v, float& lsum0, float& lsum1)
{
    (void)qz;
    // S = Q K^T (3-term)
    float s[8][4];
#pragma unroll
    for (int nt = 0; nt < 8; nt++)
#pragma unroll
        for (int e = 0; e < 4; e++) s[nt][e] = 0.f;
#pragma unroll
    for (int kd = 0; kd < 4; kd++) {
#pragma unroll
        for (int np = 0; np < 4; np++) {
            uint32_t off = SWZ128((uint32_t)((np * 16 + krow) * 128) + kd * 32 + kcb);
            uint32_t bh_[4], bl_[4];
            ldsm_x4(bh_, st + 0 + off);        // Khi
            ldsm_x4(bl_, st + 8192 + off);     // Klo
            mma_bf16(s[2 * np],     qh[kd], bh_);
            mma_bf16(s[2 * np],     qh[kd], bl_);
            mma_bf16(s[2 * np],     ql[kd], bh_);
            mma_bf16(s[2 * np + 1], qh[kd], bh_ + 2);
            mma_bf16(s[2 * np + 1], qh[kd], bl_ + 2);
            mma_bf16(s[2 * np + 1], ql[kd], bh_ + 2);
        }
    }

    // scale (+ causal mask if MASK) + row max
    float tm0 = -INFINITY, tm1 = -INFINITY;
#pragma unroll
    for (int nt = 0; nt < 8; nt++) {
        if (MASK) {
            int kg = kv0 + nt * 8 + (lid & 3) * 2;
            s[nt][0] = (kg     <= r0g) ? s[nt][0] * SCL : -INFINITY;
            s[nt][1] = (kg + 1 <= r0g) ? s[nt][1] * SCL : -INFINITY;
            s[nt][2] = (kg     <= r1g) ? s[nt][2] * SCL : -INFINITY;
            s[nt][3] = (kg + 1 <= r1g) ? s[nt][3] * SCL : -INFINITY;
        } else {
            s[nt][0] *= SCL; s[nt][1] *= SCL;
            s[nt][2] *= SCL; s[nt][3] *= SCL;
        }
        tm0 = fmaxf(tm0, fmaxf(s[nt][0], s[nt][1]));
        tm1 = fmaxf(tm1, fmaxf(s[nt][2], s[nt][3]));
    }
    tm0 = fmaxf(tm0, __shfl_xor_sync(0xffffffffu, tm0, 1));
    tm0 = fmaxf(tm0, __shfl_xor_sync(0xffffffffu, tm0, 2));
    tm1 = fmaxf(tm1, __shfl_xor_sync(0xffffffffu, tm1, 1));
    tm1 = fmaxf(tm1, __shfl_xor_sync(0xffffffffu, tm1, 2));

    float mn0 = fmaxf(m0v, tm0), mn1 = fmaxf(m1v, tm1);
    float sc0 = __expf(m0v - mn0), sc1 = __expf(m1v - mn1);
    m0v = mn0; m1v = mn1;

    // P = exp(S - m), build bf16 hi/lo A-fragments
    uint32_t pah[4][4], pal[4][4];
    float ts0 = 0.f, ts1 = 0.f;
#pragma unroll
    for (int nt = 0; nt < 8; nt++) {
        float p0 = __expf(s[nt][0] - mn0);
        float p1 = __expf(s[nt][1] - mn0);
        float p2 = __expf(s[nt][2] - mn1);
        float p3 = __expf(s[nt][3] - mn1);
        ts0 += p0 + p1; ts1 += p2 + p3;
        __nv_bfloat16 h0, h1, h2, h3, l0, l1, l2, l3;
        split1(p0, h0, l0); split1(p1, h1, l1);
        split1(p2, h2, l2); split1(p3, h3, l3);
        int kp = nt >> 1, e = (nt & 1) * 2;
        pah[kp][e] = pkbf(h0, h1); pah[kp][e + 1] = pkbf(h2, h3);
        pal[kp][e] = pkbf(l0, l1); pal[kp][e + 1] = pkbf(l2, l3);
    }
    ts0 += __shfl_xor_sync(0xffffffffu, ts0, 1);
    ts0 += __shfl_xor_sync(0xffffffffu, ts0, 2);
    ts1 += __shfl_xor_sync(0xffffffffu, ts1, 1);
    ts1 += __shfl_xor_sync(0xffffffffu, ts1, 2);
    lsum0 = lsum0 * sc0 + ts0;
    lsum1 = lsum1 * sc1 + ts1;
#pragma unroll
    for (int nt = 0; nt < 8; nt++) {
        o[nt][0] *= sc0; o[nt][1] *= sc0;
        o[nt][2] *= sc1; o[nt][3] *= sc1;
    }

    // O += P V (3-term); V fragments via ldmatrix.trans
#pragma unroll
    for (int kp = 0; kp < 4; kp++) {
#pragma unroll
        for (int np = 0; np < 4; np++) {
            uint32_t off = SWZ128((uint32_t)((kp * 16 + vrow) * 128) + np * 32 + vcb);
            uint32_t vh_[4], vl_[4];
            ldsm_x4_t(vh_, st + 16384 + off);   // Vhi
            ldsm_x4_t(vl_, st + 24576 + off);   // Vlo
            mma_bf16(o[2 * np],     pah[kp], vh_);
            mma_bf16(o[2 * np],     pah[kp], vl_);
            mma_bf16(o[2 * np],     pal[kp], vh_);
            mma_bf16(o[2 * np + 1], pah[kp], vh_ + 2);
            mma_bf16(o[2 * np + 1], pah[kp], vl_ + 2);
            mma_bf16(o[2 * np + 1], pal[kp], vh_ + 2);
        }
    }
}

__global__ __launch_bounds__(256, 1) void attn_mma(
    __nv_bfloat16* __restrict__ ohi, __nv_bfloat16* __restrict__ olo)
{
    extern __shared__ char smc[];
    uint32_t sraw = smem_u32(smc);
    uint32_t sb = (sraw + 1023u) & ~1023u;
    char* smb = smc + (sb - sraw);

    const int tid = threadIdx.x, lid = tid & 31, wq = tid >> 5;
    const int qi = blockIdx.x, bh = blockIdx.y;
    const int b = bh >> 4, h = bh & 15;
    const int q0 = qi * 128;
    const size_t base2 = ((size_t)b * Ss * Dd + (size_t)h * DH) * 2;   // bytes

    // Q load (group 0)
#pragma unroll
    for (int i = 0; i < 8; i++) {
        int idx = tid + i * 256;
        int arr = idx >> 10, c = idx & 1023;
        int row = c >> 3; uint32_t colb = (uint32_t)((c & 7) * 16);
        const char* src = (const char*)(arr ? g_qlo : g_qhi) + base2 + (size_t)(q0 + row) * 2048 + colb;
        cp16(sb + A_QZ + arr * 16384 + SWZ128((uint32_t)(row * 128) + colb), src);
    }
    CP_COMMIT();

    const char* kvb[4] = {(const char*)g_khi, (const char*)g_klo,
                          (const char*)g_vhi, (const char*)g_vlo};
    auto kvload = [&](int kt) {
        uint32_t st = sb + (kt % 3) * AT_STG;
        int kv0 = kt * 64;
#pragma unroll
        for (int i = 0; i < 8; i++) {
            int idx = tid + i * 256;
            int arr = idx >> 9, c = idx & 511;
            int row = c >> 3; uint32_t colb = (uint32_t)((c & 7) * 16);
            cp16(st + arr * 8192 + SWZ128((uint32_t)(row * 128) + colb),
                 kvb[arr] + base2 + (size_t)(kv0 + row) * 2048 + colb);
        }
    };

    const int nkt = 2 * qi + 2;
    kvload(0); CP_COMMIT();
    if (nkt > 1) { kvload(1); CP_COMMIT(); }
    CP_WAIT(2);          // Q group done
    __syncthreads();

    // Q fragments -> registers (4 dim-chunks of 16)
    uint32_t qh[4][4], ql[4][4];
    {
        const int a_row = wq * 16 + (lid & 15);
        const uint32_t a_cb = (uint32_t)(((lid >> 4) & 1) * 16);
#pragma unroll
        for (int kd = 0; kd < 4; kd++) {
            uint32_t off = SWZ128((uint32_t)(a_row * 128) + kd * 32 + a_cb);
            ldsm_x4(qh[kd], sb + A_QZ + off);
            ldsm_x4(ql[kd], sb + A_QZ + 16384 + off);
        }
    }

    float o[8][4];
#pragma unroll
    for (int nt = 0; nt < 8; nt++)
#pragma unroll
        for (int e = 0; e < 4; e++) o[nt][e] = 0.f;
    float m0v = -INFINITY, m1v = -INFINITY, lsum0 = 0.f, lsum1 = 0.f;

    const int r0g = q0 + wq * 16 + (lid >> 2);
    const int r1g = r0g + 8;
    const int mg = lid >> 3;
    const int krow = (mg >> 1) * 8 + (lid & 7);
    const uint32_t kcb = (uint32_t)((mg & 1) * 16);
    const int vrow = lid & 15;
    const uint32_t vcb = (uint32_t)((lid >> 4) * 16);

    const int ktfull = 2 * qi;     // tiles [0, ktfull) need no mask
    for (int kt = 0; kt < nkt; kt++) {
        if (kt + 2 < nkt) { kvload(kt + 2); CP_COMMIT(); CP_WAIT(2); }
        else if (kt + 1 < nkt) { CP_WAIT(1); }
        else { CP_WAIT(0); }
        __syncthreads();
        uint32_t st = sb + (kt % 3) * AT_STG;
        if (kt < ktfull)
            attn_tile<false>(st, kt * 64, r0g, r1g, lid, krow, kcb, vrow, vcb,
                             qh, ql, 0, o, m0v, m1v, lsum0, lsum1);
        else
            attn_tile<true>(st, kt * 64, r0g, r1g, lid, krow, kcb, vrow, vcb,
                            qh, ql, 0, o, m0v, m1v, lsum0, lsum1);
        __syncthreads();
    }

    // epilogue: normalize, hi/lo split, stage in smem, coalesced store
    float il0 = 1.f / lsum0, il1 = 1.f / lsum1;
    {
        int rs0 = wq * 16 + (lid >> 2);
#pragma unroll
        for (int nt = 0; nt < 8; nt++) {
            uint32_t colb = (uint32_t)(nt * 16 + (lid & 3) * 4);
            float v0 = o[nt][0] * il0, v1 = o[nt][1] * il0;
            float v2 = o[nt][2] * il1, v3 = o[nt][3] * il1;
            __nv_bfloat16 h0, h1, h2, h3, l0, l1, l2, l3;
            split1(v0, h0, l0); split1(v1, h1, l1);
            split1(v2, h2, l2); split1(v3, h3, l3);
            *(uint32_t*)(smb + A_QZ + rs0 * 128 + colb) = pkbf(h0, h1);
            *(uint32_t*)(smb + A_QZ + (rs0 + 8) * 128 + colb) = pkbf(h2, h3);
            *(uint32_t*)(smb + A_QZ + 16384 + rs0 * 128 + colb) = pkbf(l0, l1);
            *(uint32_t*)(smb + A_QZ + 16384 + (rs0 + 8) * 128 + colb) = pkbf(l2, l3);
        }
    }
    __syncthreads();
#pragma unroll
    for (int i = 0; i < 8; i++) {
        int idx = tid + i * 256;
        int arr = idx >> 10, c = idx & 1023;
        int row = c >> 3; uint32_t colb = (uint32_t)((c & 7) * 16);
        uint4 v = *(uint4*)(smb + A_QZ + arr * 16384 + row * 128 + colb);
        char* dst = (char*)(arr ? olo : ohi) + base2 + (size_t)(q0 + row) * 2048 + colb;
        *(uint4*)dst = v;
    }
}

// ---------------- launch ----------------
extern "C" void kernel_launch(void* const* d_in, const int* in_sizes, int n_in,
                              void* d_out, int out_size)
{
    const float* x  = (const float*)d_in[0];
    const float* Wq = (const float*)d_in[1];
    const float* bq = (const float*)d_in[2];
    const float* Wk = (const float*)d_in[3];
    const float* bk = (const float*)d_in[4];
    const float* Wv = (const float*)d_in[5];
    const float* bv = (const float*)d_in[6];
    const float* Wo = (const float*)d_in[7];
    const float* bo = (const float*)d_in[8];
    float* out = (float*)d_out;

    __nv_bfloat16 *xhi, *xlo, *ahi, *alo, *wthi, *wtlo;
    cudaGetSymbolAddress((void**)&xhi,  g_xhi);
    cudaGetSymbolAddress((void**)&xlo,  g_xlo);
    cudaGetSymbolAddress((void**)&ahi,  g_ahi);
    cudaGetSymbolAddress((void**)&alo,  g_alo);
    cudaGetSymbolAddress((void**)&wthi, g_wthi);
    cudaGetSymbolAddress((void**)&wtlo, g_wtlo);

    cudaFuncSetAttribute(gemm_mma<0>,
                         cudaFuncAttributeMaxDynamicSharedMemorySize, GEMM_SMEM);
    cudaFuncSetAttribute(gemm_mma<1>,
                         cudaFuncAttributeMaxDynamicSharedMemorySize, GEMM_SMEM);
    cudaFuncSetAttribute(attn_mma,
                         cudaFuncAttributeMaxDynamicSharedMemorySize, ATT_SMEM);

    transpose_split<<<dim3(32, 32, 4), dim3(32, 8)>>>(Wq, Wk, Wv, Wo, wthi, wtlo);
    split_f32<<<(MM * Dd) / 1024, 256>>>(x, xhi, xlo);

    // Fused QKV projection: one launch, outputs routed to separate q/k/v buffers
    gemm_mma<0><<<dim3(24, MM / BM), 256, GEMM_SMEM>>>(bq, bk, bv, nullptr);

    __nv_bfloat16 *ahi_p, *alo_p;
    cudaGetSymbolAddress((void**)&ahi_p, g_ahi);
    cudaGetSymbolAddress((void**)&alo_p, g_alo);
    attn_mma<<<dim3(Ss / 128, Bb * Hh), 256, ATT_SMEM>>>(ahi_p, alo_p);

    // Output projection
    gemm_mma<1><<<dim3(8, MM / BM), 256, GEMM_SMEM>>>(bo, nullptr, nullptr, out);
}